// round 2
// baseline (speedup 1.0000x reference)
#include <cuda_runtime.h>
#include <cuda_bf16.h>
#include <cstdint>

// Problem constants (fixed by the dataset)
#define NN     20000
#define EE     640000
#define ETOT   660000      // EE + NN self loops
#define GG     64
#define FIN    128
#define FOUT   128
#define HEADS  4
#define HID    64
#define HC12   256         // HEADS*HID

// ---------------------------------------------------------------------------
// Scratch (device globals; no allocation allowed)
// ---------------------------------------------------------------------------
__device__ float g_bufA[(size_t)NN * HC12];   // 20.48 MB
__device__ float g_bufB[(size_t)NN * HC12];   // 20.48 MB
__device__ float g_as[(size_t)NN * HEADS];
__device__ float g_ad[(size_t)NN * HEADS];
__device__ float g_den[(size_t)NN * HEADS];
__device__ float g_ex[(size_t)ETOT * HEADS];  // 10.56 MB
__device__ float g_gsum[GG * FOUT];
__device__ float g_gcnt[GG];

// ---------------------------------------------------------------------------
// Tiled fp32 GEMM: C[N,M] = A[N,K] * B[K,M].  BM=BN=64, BK=16, 16x16 threads,
// 4x4 microtile.  K%16==0, M%64==0 guaranteed (128/256).
// ---------------------------------------------------------------------------
__global__ __launch_bounds__(256) void gemm_kernel(
    const float* __restrict__ A, const float* __restrict__ B,
    float* __restrict__ C, int N, int K, int M)
{
    __shared__ float As[64][17];
    __shared__ float Bs[16][68];

    const int tx = threadIdx.x, ty = threadIdx.y;
    const int tid = ty * 16 + tx;
    const int rowBase = blockIdx.y * 64;
    const int colBase = blockIdx.x * 64;

    float acc[4][4];
#pragma unroll
    for (int i = 0; i < 4; i++)
#pragma unroll
        for (int j = 0; j < 4; j++) acc[i][j] = 0.f;

    for (int k0 = 0; k0 < K; k0 += 16) {
        // load A tile (64x16) as float4
        {
            int r  = tid >> 2;
            int c4 = (tid & 3) * 4;
            int gr = rowBase + r;
            float4 v = make_float4(0.f, 0.f, 0.f, 0.f);
            if (gr < N)
                v = *reinterpret_cast<const float4*>(&A[(size_t)gr * K + k0 + c4]);
            As[r][c4 + 0] = v.x; As[r][c4 + 1] = v.y;
            As[r][c4 + 2] = v.z; As[r][c4 + 3] = v.w;
        }
        // load B tile (16x64) as float4
        {
            int r  = tid >> 4;
            int c4 = (tid & 15) * 4;
            float4 v = *reinterpret_cast<const float4*>(&B[(size_t)(k0 + r) * M + colBase + c4]);
            Bs[r][c4 + 0] = v.x; Bs[r][c4 + 1] = v.y;
            Bs[r][c4 + 2] = v.z; Bs[r][c4 + 3] = v.w;
        }
        __syncthreads();

#pragma unroll
        for (int kk = 0; kk < 16; kk++) {
            float a[4], b[4];
#pragma unroll
            for (int i = 0; i < 4; i++) a[i] = As[ty * 4 + i][kk];
#pragma unroll
            for (int j = 0; j < 4; j++) b[j] = Bs[kk][tx * 4 + j];
#pragma unroll
            for (int i = 0; i < 4; i++)
#pragma unroll
                for (int j = 0; j < 4; j++) acc[i][j] += a[i] * b[j];
        }
        __syncthreads();
    }

#pragma unroll
    for (int i = 0; i < 4; i++) {
        int gr = rowBase + ty * 4 + i;
        if (gr < N) {
            float* cp = &C[(size_t)gr * M + colBase + tx * 4];
            cp[0] = acc[i][0]; cp[1] = acc[i][1];
            cp[2] = acc[i][2]; cp[3] = acc[i][3];
        }
    }
}

// ---------------------------------------------------------------------------
// alpha_s / alpha_d: warp per (node, head), dot over C channels
// ---------------------------------------------------------------------------
__global__ void alpha_kernel(const float* __restrict__ h,
                             const float* __restrict__ a_s,
                             const float* __restrict__ a_d,
                             float* __restrict__ outs, float* __restrict__ outd,
                             int H, int C)
{
    int gt   = blockIdx.x * blockDim.x + threadIdx.x;
    int wid  = gt >> 5;
    int lane = gt & 31;
    if (wid >= NN * H) return;
    int i  = wid / H;
    int hh = wid - i * H;
    const float* hp  = h + (size_t)i * H * C + hh * C;
    const float* asp = a_s + hh * C;
    const float* adp = a_d + hh * C;
    float ss = 0.f, sd = 0.f;
    for (int c = lane; c < C; c += 32) {
        float v = hp[c];
        ss += v * asp[c];
        sd += v * adp[c];
    }
#pragma unroll
    for (int o = 16; o; o >>= 1) {
        ss += __shfl_xor_sync(0xffffffffu, ss, o);
        sd += __shfl_xor_sync(0xffffffffu, sd, o);
    }
    if (lane == 0) { outs[wid] = ss; outd[wid] = sd; }
}

// ---------------------------------------------------------------------------
// Edge pass A: ex = exp(leaky_relu(as[src]+ad[dst])); denom[dst] += ex.
// Max-subtraction is skipped (e bounded; softmax ratio identical).
// ---------------------------------------------------------------------------
__global__ void edgeA_kernel(const int* __restrict__ ei,
                             const float* __restrict__ as_,
                             const float* __restrict__ ad_,
                             float* __restrict__ den, float* __restrict__ exbuf,
                             int H)
{
    int t = blockIdx.x * blockDim.x + threadIdx.x;
    if (t >= ETOT * H) return;
    int e  = t / H;
    int hh = t - e * H;
    int s, d;
    if (e < EE) { s = ei[e]; d = ei[EE + e]; }
    else        { s = e - EE; d = s; }
    float v = as_[s * H + hh] + ad_[d * H + hh];
    v = v > 0.f ? v : 0.2f * v;
    float ex = expf(v);
    exbuf[t] = ex;
    atomicAdd(&den[d * H + hh], ex);
}

// ---------------------------------------------------------------------------
// Edge pass B: out[dst] += (ex/denom[dst]) * h[src].  One warp per edge,
// float4 gathers, scalar atomic adds.
// ---------------------------------------------------------------------------
__global__ void edgeB_kernel(const int* __restrict__ ei,
                             const float* __restrict__ h,
                             const float* __restrict__ den,
                             const float* __restrict__ exbuf,
                             float* __restrict__ out, int H, int C)
{
    int gt   = blockIdx.x * blockDim.x + threadIdx.x;
    int e    = gt >> 5;
    int lane = gt & 31;
    if (e >= ETOT) return;
    int s, d;
    if (e < EE) { s = ei[e]; d = ei[EE + e]; }
    else        { s = e - EE; d = s; }
    int HC = H * C;
    const float4* hs = reinterpret_cast<const float4*>(h + (size_t)s * HC);
    float* od = out + (size_t)d * HC;
    int ngroups = HC >> 2;                 // 64 (layers 1-2) or 32 (layer 3)
    for (int g = lane; g < ngroups; g += 32) {
        int hh = (g << 2) / C;
        float alpha = exbuf[e * H + hh] / (den[d * H + hh] + 1e-16f);
        float4 v = hs[g];
        atomicAdd(&od[(g << 2) + 0], alpha * v.x);
        atomicAdd(&od[(g << 2) + 1], alpha * v.y);
        atomicAdd(&od[(g << 2) + 2], alpha * v.z);
        atomicAdd(&od[(g << 2) + 3], alpha * v.w);
    }
}

// ---------------------------------------------------------------------------
// Bias (+ optional ELU)
// ---------------------------------------------------------------------------
__global__ void bias_act_kernel(const float* __restrict__ in,
                                const float* __restrict__ b,
                                float* __restrict__ out,
                                int total, int HC, int do_elu)
{
    int t = blockIdx.x * blockDim.x + threadIdx.x;
    if (t >= total) return;
    int c = t % HC;
    float v = in[t] + b[c];
    if (do_elu) v = v > 0.f ? v : expm1f(v);
    out[t] = v;
}

// ---------------------------------------------------------------------------
// Global mean pool
// ---------------------------------------------------------------------------
__global__ void pool_cnt_kernel(const int* __restrict__ batch,
                                float* __restrict__ cnt)
{
    int t = blockIdx.x * blockDim.x + threadIdx.x;
    if (t >= NN) return;
    atomicAdd(&cnt[batch[t]], 1.f);
}

__global__ void pool_sum_kernel(const float* __restrict__ h,
                                const int* __restrict__ batch,
                                float* __restrict__ gsum)
{
    int t = blockIdx.x * blockDim.x + threadIdx.x;
    if (t >= NN * FOUT) return;
    int n = t >> 7;        // /128
    int c = t & 127;
    atomicAdd(&gsum[batch[n] * FOUT + c], h[t]);
}

__global__ void pool_div_kernel(const float* __restrict__ gsum,
                                const float* __restrict__ cnt,
                                float* __restrict__ out)
{
    int t = blockIdx.x * blockDim.x + threadIdx.x;
    if (t >= GG * FOUT) return;
    out[t] = gsum[t] / fmaxf(cnt[t >> 7], 1.f);
}

// ---------------------------------------------------------------------------
// Launch
// ---------------------------------------------------------------------------
extern "C" void kernel_launch(void* const* d_in, const int* in_sizes, int n_in,
                              void* d_out, int out_size)
{
    const float* x   = (const float*)d_in[0];
    const int*   ei  = (const int*)d_in[1];     // int32 (JAX default, no x64)
    const int*   bat = (const int*)d_in[2];     // int32
    const float* W1  = (const float*)d_in[3];
    const float* as1 = (const float*)d_in[4];
    const float* ad1 = (const float*)d_in[5];
    const float* b1  = (const float*)d_in[6];
    const float* W2  = (const float*)d_in[7];
    const float* as2 = (const float*)d_in[8];
    const float* ad2 = (const float*)d_in[9];
    const float* b2  = (const float*)d_in[10];
    const float* W3  = (const float*)d_in[11];
    const float* as3 = (const float*)d_in[12];
    const float* ad3 = (const float*)d_in[13];
    const float* b3  = (const float*)d_in[14];

    float* out     = (float*)d_out;
    float* out_emb = out;                 // [G, FOUT]
    float* out_h   = out + GG * FOUT;     // [N, FOUT]

    float *bufA, *bufB, *as_, *ad_, *den, *ex, *gsum, *gcnt;
    cudaGetSymbolAddress((void**)&bufA, g_bufA);
    cudaGetSymbolAddress((void**)&bufB, g_bufB);
    cudaGetSymbolAddress((void**)&as_,  g_as);
    cudaGetSymbolAddress((void**)&ad_,  g_ad);
    cudaGetSymbolAddress((void**)&den,  g_den);
    cudaGetSymbolAddress((void**)&ex,   g_ex);
    cudaGetSymbolAddress((void**)&gsum, g_gsum);
    cudaGetSymbolAddress((void**)&gcnt, g_gcnt);

    dim3 tb(16, 16);
    const int nby = (NN + 63) / 64;

    auto run_layer = [&](const float* xin, int K, const float* W, int M,
                         const float* a_s, const float* a_d,
                         int H, int C, float* hbuf, float* obuf) {
        dim3 gb(M / 64, nby);
        gemm_kernel<<<gb, tb>>>(xin, W, hbuf, NN, K, M);

        int nw = NN * H;
        alpha_kernel<<<(nw * 32 + 255) / 256, 256>>>(hbuf, a_s, a_d, as_, ad_, H, C);

        cudaMemsetAsync(den,  0, (size_t)NN * H * sizeof(float));
        cudaMemsetAsync(obuf, 0, (size_t)NN * M * sizeof(float));

        edgeA_kernel<<<(ETOT * H + 255) / 256, 256>>>(ei, as_, ad_, den, ex, H);
        edgeB_kernel<<<((size_t)ETOT * 32 + 255) / 256, 256>>>(ei, hbuf, den, ex, obuf, H, C);
    };

    // Layer 1: [N,128] -> [N,4,64] concat
    run_layer(x, FIN, W1, HC12, as1, ad1, HEADS, HID, bufA, bufB);
    bias_act_kernel<<<(NN * HC12 + 255) / 256, 256>>>(bufB, b1, bufB, NN * HC12, HC12, 1);

    // Layer 2: [N,256] -> [N,4,64] concat
    run_layer(bufB, HC12, W2, HC12, as2, ad2, HEADS, HID, bufA, bufB);
    bias_act_kernel<<<(NN * HC12 + 255) / 256, 256>>>(bufB, b2, bufB, NN * HC12, HC12, 1);

    // Layer 3: [N,256] -> [N,1,128], no elu; write h straight to d_out
    run_layer(bufB, HC12, W3, FOUT, as3, ad3, 1, FOUT, bufA, bufB);
    bias_act_kernel<<<(NN * FOUT + 255) / 256, 256>>>(bufB, b3, out_h, NN * FOUT, FOUT, 0);

    // Global mean pool
    cudaMemsetAsync(gsum, 0, GG * FOUT * sizeof(float));
    cudaMemsetAsync(gcnt, 0, GG * sizeof(float));
    pool_cnt_kernel<<<(NN + 255) / 256, 256>>>(bat, gcnt);
    pool_sum_kernel<<<(NN * FOUT + 255) / 256, 256>>>(out_h, bat, gsum);
    pool_div_kernel<<<(GG * FOUT + 255) / 256, 256>>>(gsum, gcnt, out_emb);
}

// round 3
// speedup vs baseline: 3.0252x; 3.0252x over previous
#include <cuda_runtime.h>
#include <cuda_bf16.h>
#include <cstdint>

#define NN     20000
#define EE     640000
#define ETOT   660000      // EE + NN self loops
#define GG     64
#define FIN    128
#define FOUT   128
#define HEADS  4
#define HID    64
#define HC12   256         // HEADS*HID

// ---------------------------------------------------------------------------
// Scratch (device globals)
// ---------------------------------------------------------------------------
__device__ float g_bufA[(size_t)NN * HC12];   // 20.48 MB (h = x @ W)
__device__ float g_bufB[(size_t)NN * HC12];   // 20.48 MB (aggregated out)
__device__ float g_as[(size_t)NN * HEADS];
__device__ float g_ad[(size_t)NN * HEADS];
__device__ float g_gsum[GG * FOUT];
__device__ float g_gcnt[GG];
__device__ int   g_deg[NN];
__device__ int   g_off[NN + 1];
__device__ int   g_cur[NN];
__device__ int   g_csr_src[ETOT];

// ---------------------------------------------------------------------------
// Tiled fp32 GEMM: C[N,M] = A[N,K] * B[K,M]
// ---------------------------------------------------------------------------
__global__ __launch_bounds__(256) void gemm_kernel(
    const float* __restrict__ A, const float* __restrict__ B,
    float* __restrict__ C, int N, int K, int M)
{
    __shared__ float As[64][17];
    __shared__ float Bs[16][68];

    const int tx = threadIdx.x, ty = threadIdx.y;
    const int tid = ty * 16 + tx;
    const int rowBase = blockIdx.y * 64;
    const int colBase = blockIdx.x * 64;

    float acc[4][4];
#pragma unroll
    for (int i = 0; i < 4; i++)
#pragma unroll
        for (int j = 0; j < 4; j++) acc[i][j] = 0.f;

    for (int k0 = 0; k0 < K; k0 += 16) {
        {
            int r  = tid >> 2;
            int c4 = (tid & 3) * 4;
            int gr = rowBase + r;
            float4 v = make_float4(0.f, 0.f, 0.f, 0.f);
            if (gr < N)
                v = *reinterpret_cast<const float4*>(&A[(size_t)gr * K + k0 + c4]);
            As[r][c4 + 0] = v.x; As[r][c4 + 1] = v.y;
            As[r][c4 + 2] = v.z; As[r][c4 + 3] = v.w;
        }
        {
            int r  = tid >> 4;
            int c4 = (tid & 15) * 4;
            float4 v = *reinterpret_cast<const float4*>(&B[(size_t)(k0 + r) * M + colBase + c4]);
            Bs[r][c4 + 0] = v.x; Bs[r][c4 + 1] = v.y;
            Bs[r][c4 + 2] = v.z; Bs[r][c4 + 3] = v.w;
        }
        __syncthreads();

#pragma unroll
        for (int kk = 0; kk < 16; kk++) {
            float a[4], b[4];
#pragma unroll
            for (int i = 0; i < 4; i++) a[i] = As[ty * 4 + i][kk];
#pragma unroll
            for (int j = 0; j < 4; j++) b[j] = Bs[kk][tx * 4 + j];
#pragma unroll
            for (int i = 0; i < 4; i++)
#pragma unroll
                for (int j = 0; j < 4; j++) acc[i][j] += a[i] * b[j];
        }
        __syncthreads();
    }

#pragma unroll
    for (int i = 0; i < 4; i++) {
        int gr = rowBase + ty * 4 + i;
        if (gr < N) {
            float* cp = &C[(size_t)gr * M + colBase + tx * 4];
            cp[0] = acc[i][0]; cp[1] = acc[i][1];
            cp[2] = acc[i][2]; cp[3] = acc[i][3];
        }
    }
}

// ---------------------------------------------------------------------------
// CSR build: histogram -> scan -> scatter (by destination)
// ---------------------------------------------------------------------------
__global__ void csr_count_kernel(const int* __restrict__ ei, int* __restrict__ deg)
{
    int t = blockIdx.x * blockDim.x + threadIdx.x;
    if (t >= ETOT) return;
    int d = (t < EE) ? ei[EE + t] : (t - EE);
    atomicAdd(&deg[d], 1);
}

__global__ void csr_scan_kernel(const int* __restrict__ deg,
                                int* __restrict__ off, int* __restrict__ cur)
{
    __shared__ int sdata[1024];
    __shared__ int carry;
    int tid = threadIdx.x;
    if (tid == 0) carry = 0;
    __syncthreads();
    for (int base = 0; base < NN; base += 1024) {
        int i = base + tid;
        int v = (i < NN) ? deg[i] : 0;
        sdata[tid] = v;
        __syncthreads();
#pragma unroll
        for (int o = 1; o < 1024; o <<= 1) {
            int t = (tid >= o) ? sdata[tid - o] : 0;
            __syncthreads();
            sdata[tid] += t;
            __syncthreads();
        }
        int excl = sdata[tid] - v + carry;
        if (i < NN) { off[i] = excl; cur[i] = excl; }
        __syncthreads();
        if (tid == 1023) carry += sdata[1023];
        __syncthreads();
    }
    if (tid == 0) off[NN] = ETOT;
}

__global__ void csr_scatter_kernel(const int* __restrict__ ei,
                                   int* __restrict__ cur, int* __restrict__ csr_src)
{
    int t = blockIdx.x * blockDim.x + threadIdx.x;
    if (t >= ETOT) return;
    int s, d;
    if (t < EE) { s = ei[t]; d = ei[EE + t]; }
    else        { s = t - EE; d = s; }
    int pos = atomicAdd(&cur[d], 1);
    csr_src[pos] = s;
}

// ---------------------------------------------------------------------------
// alpha_s / alpha_d: warp per (node, head)
// ---------------------------------------------------------------------------
__global__ void alpha_kernel(const float* __restrict__ h,
                             const float* __restrict__ a_s,
                             const float* __restrict__ a_d,
                             float* __restrict__ outs, float* __restrict__ outd,
                             int H, int C)
{
    int gt   = blockIdx.x * blockDim.x + threadIdx.x;
    int wid  = gt >> 5;
    int lane = gt & 31;
    if (wid >= NN * H) return;
    int i  = wid / H;
    int hh = wid - i * H;
    const float* hp  = h + (size_t)i * H * C + hh * C;
    const float* asp = a_s + hh * C;
    const float* adp = a_d + hh * C;
    float ss = 0.f, sd = 0.f;
    for (int c = lane; c < C; c += 32) {
        float v = hp[c];
        ss += v * asp[c];
        sd += v * adp[c];
    }
#pragma unroll
    for (int o = 16; o; o >>= 1) {
        ss += __shfl_xor_sync(0xffffffffu, ss, o);
        sd += __shfl_xor_sync(0xffffffffu, sd, o);
    }
    if (lane == 0) { outs[wid] = ss; outd[wid] = sd; }
}

// ---------------------------------------------------------------------------
// Fused GAT aggregation (H=4, C=64): warp per dst node.
// Lane l handles float4 groups l and l+32 of the 256-channel row:
//   group1 channels [l*4, l*4+4)        -> head h1 = l/16   (0 or 1)
//   group2 channels [128+l*4, ...)      -> head h2 = 2+l/16 (2 or 3)
// Softmax (no max-subtraction; e bounded), bias + optional ELU fused.
// ---------------------------------------------------------------------------
__global__ __launch_bounds__(256) void gat_gather4_kernel(
    const int* __restrict__ off, const int* __restrict__ csr_src,
    const float* __restrict__ h,
    const float* __restrict__ as_, const float* __restrict__ ad_,
    const float* __restrict__ bias, float* __restrict__ out, int do_elu)
{
    int gt   = blockIdx.x * blockDim.x + threadIdx.x;
    int d    = gt >> 5;
    int lane = gt & 31;
    if (d >= NN) return;

    const bool lo = (lane < 16);
    float4 ad4 = *reinterpret_cast<const float4*>(&ad_[d * 4]);
    float adv1 = lo ? ad4.x : ad4.y;
    float adv2 = lo ? ad4.z : ad4.w;

    float4 acc1 = make_float4(0.f, 0.f, 0.f, 0.f);
    float4 acc2 = make_float4(0.f, 0.f, 0.f, 0.f);
    float den1 = 0.f, den2 = 0.f;

    int a   = off[d];
    int end = off[d + 1];
    for (; a < end; a++) {
        int s = csr_src[a];
        float4 as4 = *reinterpret_cast<const float4*>(&as_[s * 4]);
        float e1 = (lo ? as4.x : as4.y) + adv1;
        float e2 = (lo ? as4.z : as4.w) + adv2;
        e1 = e1 > 0.f ? e1 : 0.2f * e1;
        e2 = e2 > 0.f ? e2 : 0.2f * e2;
        float ex1 = __expf(e1);
        float ex2 = __expf(e2);
        const float4* hp = reinterpret_cast<const float4*>(h + (size_t)s * HC12);
        float4 v1 = hp[lane];
        float4 v2 = hp[lane + 32];
        acc1.x += ex1 * v1.x; acc1.y += ex1 * v1.y;
        acc1.z += ex1 * v1.z; acc1.w += ex1 * v1.w;
        acc2.x += ex2 * v2.x; acc2.y += ex2 * v2.y;
        acc2.z += ex2 * v2.z; acc2.w += ex2 * v2.w;
        den1 += ex1;
        den2 += ex2;
    }

    float r1 = 1.f / (den1 + 1e-16f);
    float r2 = 1.f / (den2 + 1e-16f);
    float4 b1 = *reinterpret_cast<const float4*>(&bias[lane * 4]);
    float4 b2 = *reinterpret_cast<const float4*>(&bias[128 + lane * 4]);
    float4 o1, o2;
    o1.x = acc1.x * r1 + b1.x; o1.y = acc1.y * r1 + b1.y;
    o1.z = acc1.z * r1 + b1.z; o1.w = acc1.w * r1 + b1.w;
    o2.x = acc2.x * r2 + b2.x; o2.y = acc2.y * r2 + b2.y;
    o2.z = acc2.z * r2 + b2.z; o2.w = acc2.w * r2 + b2.w;
    if (do_elu) {
        o1.x = o1.x > 0.f ? o1.x : expm1f(o1.x);
        o1.y = o1.y > 0.f ? o1.y : expm1f(o1.y);
        o1.z = o1.z > 0.f ? o1.z : expm1f(o1.z);
        o1.w = o1.w > 0.f ? o1.w : expm1f(o1.w);
        o2.x = o2.x > 0.f ? o2.x : expm1f(o2.x);
        o2.y = o2.y > 0.f ? o2.y : expm1f(o2.y);
        o2.z = o2.z > 0.f ? o2.z : expm1f(o2.z);
        o2.w = o2.w > 0.f ? o2.w : expm1f(o2.w);
    }
    float4* op = reinterpret_cast<float4*>(out + (size_t)d * HC12);
    op[lane]      = o1;
    op[lane + 32] = o2;
}

// ---------------------------------------------------------------------------
// Fused GAT aggregation (H=1, C=128): warp per dst node, lane = float4 group.
// ---------------------------------------------------------------------------
__global__ __launch_bounds__(256) void gat_gather1_kernel(
    const int* __restrict__ off, const int* __restrict__ csr_src,
    const float* __restrict__ h,
    const float* __restrict__ as_, const float* __restrict__ ad_,
    const float* __restrict__ bias, float* __restrict__ out)
{
    int gt   = blockIdx.x * blockDim.x + threadIdx.x;
    int d    = gt >> 5;
    int lane = gt & 31;
    if (d >= NN) return;

    float adv = ad_[d];
    float4 acc = make_float4(0.f, 0.f, 0.f, 0.f);
    float den = 0.f;

    int a   = off[d];
    int end = off[d + 1];
    for (; a < end; a++) {
        int s = csr_src[a];
        float e = as_[s] + adv;
        e = e > 0.f ? e : 0.2f * e;
        float ex = __expf(e);
        float4 v = reinterpret_cast<const float4*>(h + (size_t)s * FOUT)[lane];
        acc.x += ex * v.x; acc.y += ex * v.y;
        acc.z += ex * v.z; acc.w += ex * v.w;
        den += ex;
    }

    float r = 1.f / (den + 1e-16f);
    float4 b = *reinterpret_cast<const float4*>(&bias[lane * 4]);
    float4 o;
    o.x = acc.x * r + b.x; o.y = acc.y * r + b.y;
    o.z = acc.z * r + b.z; o.w = acc.w * r + b.w;
    reinterpret_cast<float4*>(out + (size_t)d * FOUT)[lane] = o;
}

// ---------------------------------------------------------------------------
// Global mean pool
// ---------------------------------------------------------------------------
__global__ void pool_cnt_kernel(const int* __restrict__ batch, float* __restrict__ cnt)
{
    int t = blockIdx.x * blockDim.x + threadIdx.x;
    if (t >= NN) return;
    atomicAdd(&cnt[batch[t]], 1.f);
}

__global__ void pool_sum_kernel(const float* __restrict__ h,
                                const int* __restrict__ batch,
                                float* __restrict__ gsum)
{
    int t = blockIdx.x * blockDim.x + threadIdx.x;
    if (t >= NN * FOUT) return;
    int n = t >> 7;
    int c = t & 127;
    atomicAdd(&gsum[batch[n] * FOUT + c], h[t]);
}

__global__ void pool_div_kernel(const float* __restrict__ gsum,
                                const float* __restrict__ cnt,
                                float* __restrict__ out)
{
    int t = blockIdx.x * blockDim.x + threadIdx.x;
    if (t >= GG * FOUT) return;
    out[t] = gsum[t] / fmaxf(cnt[t >> 7], 1.f);
}

// ---------------------------------------------------------------------------
// Launch
// ---------------------------------------------------------------------------
extern "C" void kernel_launch(void* const* d_in, const int* in_sizes, int n_in,
                              void* d_out, int out_size)
{
    const float* x   = (const float*)d_in[0];
    const int*   ei  = (const int*)d_in[1];
    const int*   bat = (const int*)d_in[2];
    const float* W1  = (const float*)d_in[3];
    const float* as1 = (const float*)d_in[4];
    const float* ad1 = (const float*)d_in[5];
    const float* b1  = (const float*)d_in[6];
    const float* W2  = (const float*)d_in[7];
    const float* as2 = (const float*)d_in[8];
    const float* ad2 = (const float*)d_in[9];
    const float* b2  = (const float*)d_in[10];
    const float* W3  = (const float*)d_in[11];
    const float* as3 = (const float*)d_in[12];
    const float* ad3 = (const float*)d_in[13];
    const float* b3  = (const float*)d_in[14];

    float* out     = (float*)d_out;
    float* out_emb = out;                 // [G, FOUT]
    float* out_h   = out + GG * FOUT;     // [N, FOUT]

    float *bufA, *bufB, *as_, *ad_, *gsum, *gcnt;
    int *deg, *off, *cur, *csr_src;
    cudaGetSymbolAddress((void**)&bufA, g_bufA);
    cudaGetSymbolAddress((void**)&bufB, g_bufB);
    cudaGetSymbolAddress((void**)&as_,  g_as);
    cudaGetSymbolAddress((void**)&ad_,  g_ad);
    cudaGetSymbolAddress((void**)&gsum, g_gsum);
    cudaGetSymbolAddress((void**)&gcnt, g_gcnt);
    cudaGetSymbolAddress((void**)&deg,  g_deg);
    cudaGetSymbolAddress((void**)&off,  g_off);
    cudaGetSymbolAddress((void**)&cur,  g_cur);
    cudaGetSymbolAddress((void**)&csr_src, g_csr_src);

    // --- CSR build ---
    cudaMemsetAsync(deg, 0, NN * sizeof(int));
    csr_count_kernel<<<(ETOT + 255) / 256, 256>>>(ei, deg);
    csr_scan_kernel<<<1, 1024>>>(deg, off, cur);
    csr_scatter_kernel<<<(ETOT + 255) / 256, 256>>>(ei, cur, csr_src);

    dim3 tb(16, 16);
    const int nby = (NN + 63) / 64;
    const int gatherGrid = (NN * 32 + 255) / 256;

    // --- Layer 1 ---
    gemm_kernel<<<dim3(HC12 / 64, nby), tb>>>(x, W1, bufA, NN, FIN, HC12);
    alpha_kernel<<<(NN * HEADS * 32 + 255) / 256, 256>>>(bufA, as1, ad1, as_, ad_, HEADS, HID);
    gat_gather4_kernel<<<gatherGrid, 256>>>(off, csr_src, bufA, as_, ad_, b1, bufB, 1);

    // --- Layer 2 ---
    gemm_kernel<<<dim3(HC12 / 64, nby), tb>>>(bufB, W2, bufA, NN, HC12, HC12);
    alpha_kernel<<<(NN * HEADS * 32 + 255) / 256, 256>>>(bufA, as2, ad2, as_, ad_, HEADS, HID);
    gat_gather4_kernel<<<gatherGrid, 256>>>(off, csr_src, bufA, as_, ad_, b2, bufB, 1);

    // --- Layer 3 ---
    gemm_kernel<<<dim3(FOUT / 64, nby), tb>>>(bufB, W3, bufA, NN, HC12, FOUT);
    alpha_kernel<<<(NN * 32 + 255) / 256, 256>>>(bufA, as3, ad3, as_, ad_, 1, FOUT);
    gat_gather1_kernel<<<gatherGrid, 256>>>(off, csr_src, bufA, as_, ad_, b3, out_h);

    // --- Global mean pool ---
    cudaMemsetAsync(gsum, 0, GG * FOUT * sizeof(float));
    cudaMemsetAsync(gcnt, 0, GG * sizeof(float));
    pool_cnt_kernel<<<(NN + 255) / 256, 256>>>(bat, gcnt);
    pool_sum_kernel<<<(NN * FOUT + 255) / 256, 256>>>(out_h, bat, gsum);
    pool_div_kernel<<<(GG * FOUT + 255) / 256, 256>>>(gsum, gcnt, out_emb);
}

// round 4
// speedup vs baseline: 4.0402x; 1.3355x over previous
#include <cuda_runtime.h>
#include <cuda_bf16.h>
#include <cstdint>

#define NN     20000
#define EE     640000
#define ETOT   660000      // EE + NN self loops
#define GG     64
#define FIN    128
#define FOUT   128
#define HEADS  4
#define HID    64
#define HC12   256         // HEADS*HID

// ---------------------------------------------------------------------------
// Scratch (device globals)
// ---------------------------------------------------------------------------
__device__ float g_bufA[(size_t)NN * HC12];   // h = x @ W
__device__ float g_bufB[(size_t)NN * HC12];   // aggregated out
__device__ float g_as[(size_t)NN * HEADS];
__device__ float g_ad[(size_t)NN * HEADS];
__device__ float g_gsum[GG * FOUT];
__device__ float g_gcnt[GG];
__device__ int   g_deg[NN];
__device__ int   g_off[NN + 1];
__device__ int   g_cur[NN];
__device__ int   g_csr_src[ETOT];

// ---------------------------------------------------------------------------
// TF32 helpers
// ---------------------------------------------------------------------------
__device__ __forceinline__ float to_tf32(float x) {
    uint32_t u;
    asm("cvt.rna.tf32.f32 %0, %1;" : "=r"(u) : "f"(x));
    return __uint_as_float(u);
}

__device__ __forceinline__ void mma_tf32(float* c, const uint32_t* a, const uint32_t* b) {
    asm volatile(
        "mma.sync.aligned.m16n8k8.row.col.f32.tf32.tf32.f32 "
        "{%0,%1,%2,%3}, {%4,%5,%6,%7}, {%8,%9}, {%0,%1,%2,%3};"
        : "+f"(c[0]), "+f"(c[1]), "+f"(c[2]), "+f"(c[3])
        : "r"(a[0]), "r"(a[1]), "r"(a[2]), "r"(a[3]), "r"(b[0]), "r"(b[1]));
}

// ---------------------------------------------------------------------------
// TF32 tensor-core GEMM: C[N,M] = A[N,K] * B[K,M]
// BM=128, BN=64, BK=16; 8 warps, each 32x32; mma m16n8k8.
// ---------------------------------------------------------------------------
__global__ __launch_bounds__(256) void gemm_tc_kernel(
    const float* __restrict__ A, const float* __restrict__ B,
    float* __restrict__ C, int N, int K, int M)
{
    __shared__ float As[128][20];  // [m][k], stride 20 -> conflict-free frag loads
    __shared__ float Bs[16][72];   // [k][n], stride 72 -> conflict-free frag loads

    const int tid  = threadIdx.x;
    const int lane = tid & 31;
    const int warp = tid >> 5;
    const int wr   = (warp & 3) * 32;   // warp row base within tile
    const int wc   = (warp >> 2) * 32;  // warp col base within tile
    const int rowBase = blockIdx.y * 128;
    const int colBase = blockIdx.x * 64;
    const int g  = lane >> 2;   // groupID (0..7)
    const int tg = lane & 3;    // threadID in group (0..3)

    float acc[2][4][4];
#pragma unroll
    for (int i = 0; i < 2; i++)
#pragma unroll
        for (int j = 0; j < 4; j++)
#pragma unroll
            for (int k = 0; k < 4; k++) acc[i][j][k] = 0.f;

    for (int k0 = 0; k0 < K; k0 += 16) {
        // A tile: 128x16 fp32 = 512 float4, 2 per thread (convert to tf32)
#pragma unroll
        for (int l = 0; l < 2; l++) {
            int i  = tid + l * 256;
            int r  = i >> 2;
            int c4 = (i & 3) * 4;
            int gr = rowBase + r;
            float4 v = make_float4(0.f, 0.f, 0.f, 0.f);
            if (gr < N) v = *reinterpret_cast<const float4*>(&A[(size_t)gr * K + k0 + c4]);
            v.x = to_tf32(v.x); v.y = to_tf32(v.y);
            v.z = to_tf32(v.z); v.w = to_tf32(v.w);
            *reinterpret_cast<float4*>(&As[r][c4]) = v;
        }
        // B tile: 16x64 = 256 float4, 1 per thread
        {
            int r  = tid >> 4;
            int c4 = (tid & 15) * 4;
            float4 v = *reinterpret_cast<const float4*>(&B[(size_t)(k0 + r) * M + colBase + c4]);
            v.x = to_tf32(v.x); v.y = to_tf32(v.y);
            v.z = to_tf32(v.z); v.w = to_tf32(v.w);
            *reinterpret_cast<float4*>(&Bs[r][c4]) = v;
        }
        __syncthreads();

#pragma unroll
        for (int kk = 0; kk < 16; kk += 8) {
            uint32_t a[2][4], b[4][2];
#pragma unroll
            for (int i = 0; i < 2; i++) {
                int r0 = wr + i * 16 + g;
                a[i][0] = __float_as_uint(As[r0][kk + tg]);
                a[i][1] = __float_as_uint(As[r0 + 8][kk + tg]);
                a[i][2] = __float_as_uint(As[r0][kk + 4 + tg]);
                a[i][3] = __float_as_uint(As[r0 + 8][kk + 4 + tg]);
            }
#pragma unroll
            for (int j = 0; j < 4; j++) {
                int c0 = wc + j * 8 + g;
                b[j][0] = __float_as_uint(Bs[kk + tg][c0]);
                b[j][1] = __float_as_uint(Bs[kk + 4 + tg][c0]);
            }
#pragma unroll
            for (int i = 0; i < 2; i++)
#pragma unroll
                for (int j = 0; j < 4; j++)
                    mma_tf32(acc[i][j], a[i], b[j]);
        }
        __syncthreads();
    }

    // Writeback: c0,c1 -> (row, 2*tg), (row, 2*tg+1); c2,c3 -> row+8
#pragma unroll
    for (int i = 0; i < 2; i++) {
        int r0 = rowBase + wr + i * 16 + g;
#pragma unroll
        for (int j = 0; j < 4; j++) {
            int c0 = colBase + wc + j * 8 + tg * 2;
            if (r0 < N) {
                float2 v = make_float2(acc[i][j][0], acc[i][j][1]);
                *reinterpret_cast<float2*>(&C[(size_t)r0 * M + c0]) = v;
            }
            if (r0 + 8 < N) {
                float2 v = make_float2(acc[i][j][2], acc[i][j][3]);
                *reinterpret_cast<float2*>(&C[(size_t)(r0 + 8) * M + c0]) = v;
            }
        }
    }
}

// ---------------------------------------------------------------------------
// CSR build: histogram -> fast scan -> scatter
// ---------------------------------------------------------------------------
__global__ void csr_count_kernel(const int* __restrict__ ei, int* __restrict__ deg)
{
    int t = blockIdx.x * blockDim.x + threadIdx.x;
    if (t >= ETOT) return;
    int d = (t < EE) ? ei[EE + t] : (t - EE);
    atomicAdd(&deg[d], 1);
}

// single block, 1024 threads, 20 elems/thread; shuffle 2-level scan
__global__ __launch_bounds__(1024) void csr_scan_kernel(
    const int* __restrict__ deg, int* __restrict__ off, int* __restrict__ cur)
{
    const int PER = 20;
    __shared__ int warpSums[32];
    int t    = threadIdx.x;
    int lane = t & 31, wid = t >> 5;
    int base = t * PER;

    int v[PER];
    int s = 0;
#pragma unroll
    for (int i = 0; i < PER; i++) {
        int idx = base + i;
        int x = (idx < NN) ? deg[idx] : 0;
        v[i] = s;          // exclusive within thread
        s += x;
    }
    int incl = s;
#pragma unroll
    for (int o = 1; o < 32; o <<= 1) {
        int u = __shfl_up_sync(0xffffffffu, incl, o);
        if (lane >= o) incl += u;
    }
    if (lane == 31) warpSums[wid] = incl;
    __syncthreads();
    if (wid == 0) {
        int ws = warpSums[lane];
#pragma unroll
        for (int o = 1; o < 32; o <<= 1) {
            int u = __shfl_up_sync(0xffffffffu, ws, o);
            if (lane >= o) ws += u;
        }
        warpSums[lane] = ws;
    }
    __syncthreads();
    int warpPrefix  = (wid == 0) ? 0 : warpSums[wid - 1];
    int threadExcl  = warpPrefix + incl - s;
#pragma unroll
    for (int i = 0; i < PER; i++) {
        int idx = base + i;
        if (idx < NN) {
            int e = threadExcl + v[i];
            off[idx] = e;
            cur[idx] = e;
        }
    }
    if (t == 0) off[NN] = ETOT;
}

__global__ void csr_scatter_kernel(const int* __restrict__ ei,
                                   int* __restrict__ cur, int* __restrict__ csr_src)
{
    int t = blockIdx.x * blockDim.x + threadIdx.x;
    if (t >= ETOT) return;
    int s, d;
    if (t < EE) { s = ei[t]; d = ei[EE + t]; }
    else        { s = t - EE; d = s; }
    int pos = atomicAdd(&cur[d], 1);
    csr_src[pos] = s;
}

// ---------------------------------------------------------------------------
// alpha_s / alpha_d: warp per (node, head)
// ---------------------------------------------------------------------------
__global__ void alpha_kernel(const float* __restrict__ h,
                             const float* __restrict__ a_s,
                             const float* __restrict__ a_d,
                             float* __restrict__ outs, float* __restrict__ outd,
                             int H, int C)
{
    int gt   = blockIdx.x * blockDim.x + threadIdx.x;
    int wid  = gt >> 5;
    int lane = gt & 31;
    if (wid >= NN * H) return;
    int i  = wid / H;
    int hh = wid - i * H;
    const float* hp  = h + (size_t)i * H * C + hh * C;
    const float* asp = a_s + hh * C;
    const float* adp = a_d + hh * C;
    float ss = 0.f, sd = 0.f;
    for (int c = lane; c < C; c += 32) {
        float v = hp[c];
        ss += v * asp[c];
        sd += v * adp[c];
    }
#pragma unroll
    for (int o = 16; o; o >>= 1) {
        ss += __shfl_xor_sync(0xffffffffu, ss, o);
        sd += __shfl_xor_sync(0xffffffffu, sd, o);
    }
    if (lane == 0) { outs[wid] = ss; outd[wid] = sd; }
}

// ---------------------------------------------------------------------------
// Fused GAT aggregation (H=4, C=64): warp per dst node.
// ---------------------------------------------------------------------------
__global__ __launch_bounds__(256) void gat_gather4_kernel(
    const int* __restrict__ off, const int* __restrict__ csr_src,
    const float* __restrict__ h,
    const float* __restrict__ as_, const float* __restrict__ ad_,
    const float* __restrict__ bias, float* __restrict__ out, int do_elu)
{
    int gt   = blockIdx.x * blockDim.x + threadIdx.x;
    int d    = gt >> 5;
    int lane = gt & 31;
    if (d >= NN) return;

    const bool lo = (lane < 16);
    float4 ad4 = *reinterpret_cast<const float4*>(&ad_[d * 4]);
    float adv1 = lo ? ad4.x : ad4.y;
    float adv2 = lo ? ad4.z : ad4.w;

    float4 acc1 = make_float4(0.f, 0.f, 0.f, 0.f);
    float4 acc2 = make_float4(0.f, 0.f, 0.f, 0.f);
    float den1 = 0.f, den2 = 0.f;

    int a   = off[d];
    int end = off[d + 1];
    for (; a < end; a++) {
        int s = csr_src[a];
        float4 as4 = *reinterpret_cast<const float4*>(&as_[s * 4]);
        float e1 = (lo ? as4.x : as4.y) + adv1;
        float e2 = (lo ? as4.z : as4.w) + adv2;
        e1 = e1 > 0.f ? e1 : 0.2f * e1;
        e2 = e2 > 0.f ? e2 : 0.2f * e2;
        float ex1 = __expf(e1);
        float ex2 = __expf(e2);
        const float4* hp = reinterpret_cast<const float4*>(h + (size_t)s * HC12);
        float4 v1 = hp[lane];
        float4 v2 = hp[lane + 32];
        acc1.x += ex1 * v1.x; acc1.y += ex1 * v1.y;
        acc1.z += ex1 * v1.z; acc1.w += ex1 * v1.w;
        acc2.x += ex2 * v2.x; acc2.y += ex2 * v2.y;
        acc2.z += ex2 * v2.z; acc2.w += ex2 * v2.w;
        den1 += ex1;
        den2 += ex2;
    }

    float r1 = 1.f / (den1 + 1e-16f);
    float r2 = 1.f / (den2 + 1e-16f);
    float4 b1 = *reinterpret_cast<const float4*>(&bias[lane * 4]);
    float4 b2 = *reinterpret_cast<const float4*>(&bias[128 + lane * 4]);
    float4 o1, o2;
    o1.x = acc1.x * r1 + b1.x; o1.y = acc1.y * r1 + b1.y;
    o1.z = acc1.z * r1 + b1.z; o1.w = acc1.w * r1 + b1.w;
    o2.x = acc2.x * r2 + b2.x; o2.y = acc2.y * r2 + b2.y;
    o2.z = acc2.z * r2 + b2.z; o2.w = acc2.w * r2 + b2.w;
    if (do_elu) {
        o1.x = o1.x > 0.f ? o1.x : expm1f(o1.x);
        o1.y = o1.y > 0.f ? o1.y : expm1f(o1.y);
        o1.z = o1.z > 0.f ? o1.z : expm1f(o1.z);
        o1.w = o1.w > 0.f ? o1.w : expm1f(o1.w);
        o2.x = o2.x > 0.f ? o2.x : expm1f(o2.x);
        o2.y = o2.y > 0.f ? o2.y : expm1f(o2.y);
        o2.z = o2.z > 0.f ? o2.z : expm1f(o2.z);
        o2.w = o2.w > 0.f ? o2.w : expm1f(o2.w);
    }
    float4* op = reinterpret_cast<float4*>(out + (size_t)d * HC12);
    op[lane]      = o1;
    op[lane + 32] = o2;
}

// ---------------------------------------------------------------------------
// Fused GAT aggregation (H=1, C=128)
// ---------------------------------------------------------------------------
__global__ __launch_bounds__(256) void gat_gather1_kernel(
    const int* __restrict__ off, const int* __restrict__ csr_src,
    const float* __restrict__ h,
    const float* __restrict__ as_, const float* __restrict__ ad_,
    const float* __restrict__ bias, float* __restrict__ out)
{
    int gt   = blockIdx.x * blockDim.x + threadIdx.x;
    int d    = gt >> 5;
    int lane = gt & 31;
    if (d >= NN) return;

    float adv = ad_[d];
    float4 acc = make_float4(0.f, 0.f, 0.f, 0.f);
    float den = 0.f;

    int a   = off[d];
    int end = off[d + 1];
    for (; a < end; a++) {
        int s = csr_src[a];
        float e = as_[s] + adv;
        e = e > 0.f ? e : 0.2f * e;
        float ex = __expf(e);
        float4 v = reinterpret_cast<const float4*>(h + (size_t)s * FOUT)[lane];
        acc.x += ex * v.x; acc.y += ex * v.y;
        acc.z += ex * v.z; acc.w += ex * v.w;
        den += ex;
    }

    float r = 1.f / (den + 1e-16f);
    float4 b = *reinterpret_cast<const float4*>(&bias[lane * 4]);
    float4 o;
    o.x = acc.x * r + b.x; o.y = acc.y * r + b.y;
    o.z = acc.z * r + b.z; o.w = acc.w * r + b.w;
    reinterpret_cast<float4*>(out + (size_t)d * FOUT)[lane] = o;
}

// ---------------------------------------------------------------------------
// Global mean pool
// ---------------------------------------------------------------------------
__global__ void pool_cnt_kernel(const int* __restrict__ batch, float* __restrict__ cnt)
{
    int t = blockIdx.x * blockDim.x + threadIdx.x;
    if (t >= NN) return;
    atomicAdd(&cnt[batch[t]], 1.f);
}

__global__ void pool_sum_kernel(const float* __restrict__ h,
                                const int* __restrict__ batch,
                                float* __restrict__ gsum)
{
    int t = blockIdx.x * blockDim.x + threadIdx.x;
    if (t >= NN * FOUT) return;
    int n = t >> 7;
    int c = t & 127;
    atomicAdd(&gsum[batch[n] * FOUT + c], h[t]);
}

__global__ void pool_div_kernel(const float* __restrict__ gsum,
                                const float* __restrict__ cnt,
                                float* __restrict__ out)
{
    int t = blockIdx.x * blockDim.x + threadIdx.x;
    if (t >= GG * FOUT) return;
    out[t] = gsum[t] / fmaxf(cnt[t >> 7], 1.f);
}

// ---------------------------------------------------------------------------
// Launch
// ---------------------------------------------------------------------------
extern "C" void kernel_launch(void* const* d_in, const int* in_sizes, int n_in,
                              void* d_out, int out_size)
{
    const float* x   = (const float*)d_in[0];
    const int*   ei  = (const int*)d_in[1];
    const int*   bat = (const int*)d_in[2];
    const float* W1  = (const float*)d_in[3];
    const float* as1 = (const float*)d_in[4];
    const float* ad1 = (const float*)d_in[5];
    const float* b1  = (const float*)d_in[6];
    const float* W2  = (const float*)d_in[7];
    const float* as2 = (const float*)d_in[8];
    const float* ad2 = (const float*)d_in[9];
    const float* b2  = (const float*)d_in[10];
    const float* W3  = (const float*)d_in[11];
    const float* as3 = (const float*)d_in[12];
    const float* ad3 = (const float*)d_in[13];
    const float* b3  = (const float*)d_in[14];

    float* out     = (float*)d_out;
    float* out_emb = out;                 // [G, FOUT]
    float* out_h   = out + GG * FOUT;     // [N, FOUT]

    float *bufA, *bufB, *as_, *ad_, *gsum, *gcnt;
    int *deg, *off, *cur, *csr_src;
    cudaGetSymbolAddress((void**)&bufA, g_bufA);
    cudaGetSymbolAddress((void**)&bufB, g_bufB);
    cudaGetSymbolAddress((void**)&as_,  g_as);
    cudaGetSymbolAddress((void**)&ad_,  g_ad);
    cudaGetSymbolAddress((void**)&gsum, g_gsum);
    cudaGetSymbolAddress((void**)&gcnt, g_gcnt);
    cudaGetSymbolAddress((void**)&deg,  g_deg);
    cudaGetSymbolAddress((void**)&off,  g_off);
    cudaGetSymbolAddress((void**)&cur,  g_cur);
    cudaGetSymbolAddress((void**)&csr_src, g_csr_src);

    // --- CSR build ---
    cudaMemsetAsync(deg, 0, NN * sizeof(int));
    csr_count_kernel<<<(ETOT + 255) / 256, 256>>>(ei, deg);
    csr_scan_kernel<<<1, 1024>>>(deg, off, cur);
    csr_scatter_kernel<<<(ETOT + 255) / 256, 256>>>(ei, cur, csr_src);

    const int nby = (NN + 127) / 128;
    const int gatherGrid = (NN * 32 + 255) / 256;

    // --- Layer 1 ---
    gemm_tc_kernel<<<dim3(HC12 / 64, nby), 256>>>(x, W1, bufA, NN, FIN, HC12);
    alpha_kernel<<<(NN * HEADS * 32 + 255) / 256, 256>>>(bufA, as1, ad1, as_, ad_, HEADS, HID);
    gat_gather4_kernel<<<gatherGrid, 256>>>(off, csr_src, bufA, as_, ad_, b1, bufB, 1);

    // --- Layer 2 ---
    gemm_tc_kernel<<<dim3(HC12 / 64, nby), 256>>>(bufB, W2, bufA, NN, HC12, HC12);
    alpha_kernel<<<(NN * HEADS * 32 + 255) / 256, 256>>>(bufA, as2, ad2, as_, ad_, HEADS, HID);
    gat_gather4_kernel<<<gatherGrid, 256>>>(off, csr_src, bufA, as_, ad_, b2, bufB, 1);

    // --- Layer 3 ---
    gemm_tc_kernel<<<dim3(FOUT / 64, nby), 256>>>(bufB, W3, bufA, NN, HC12, FOUT);
    alpha_kernel<<<(NN * 32 + 255) / 256, 256>>>(bufA, as3, ad3, as_, ad_, 1, FOUT);
    gat_gather1_kernel<<<gatherGrid, 256>>>(off, csr_src, bufA, as_, ad_, b3, out_h);

    // --- Global mean pool ---
    cudaMemsetAsync(gsum, 0, GG * FOUT * sizeof(float));
    cudaMemsetAsync(gcnt, 0, GG * sizeof(float));
    pool_cnt_kernel<<<(NN + 255) / 256, 256>>>(bat, gcnt);
    pool_sum_kernel<<<(NN * FOUT + 255) / 256, 256>>>(out_h, bat, gsum);
    pool_div_kernel<<<(GG * FOUT + 255) / 256, 256>>>(gsum, gcnt, out_emb);
}